// round 2
// baseline (speedup 1.0000x reference)
#include <cuda_runtime.h>
#include <cstdint>

// probs: float32 [50,50,50,50] -> 6,250,000 floats (row-major)
// X:     int32   [8,000,000, 4]   (reference says int64, but JAX default x64=off
//                                  downcasts randint to int32)
// out:   float32 [8,000,000]
//
// out[i] = probs[ ((X0*50 + X1)*50 + X2)*50 + X3 ]

__global__ __launch_bounds__(256) void joint_cat_gather(
    const float* __restrict__ probs,
    const int4* __restrict__ X,   // one int4 = one sample's 4 indices (16B)
    float* __restrict__ out,
    int n)
{
    int i = blockIdx.x * blockDim.x + threadIdx.x;
    if (i >= n) return;

    int4 x = X[i];  // coalesced 16B load
    int idx = x.x * 50 + x.y;
    idx = idx * 50 + x.z;
    idx = idx * 50 + x.w;

    out[i] = __ldg(probs + idx);
}

extern "C" void kernel_launch(void* const* d_in, const int* in_sizes, int n_in,
                              void* d_out, int out_size)
{
    const float* probs = (const float*)d_in[0];
    const int4* X = (const int4*)d_in[1];
    float* out = (float*)d_out;

    int n = out_size;  // 8,000,000 samples
    int threads = 256;
    int blocks = (n + threads - 1) / threads;
    joint_cat_gather<<<blocks, threads>>>(probs, X, out, n);
}